// round 2
// baseline (speedup 1.0000x reference)
#include <cuda_runtime.h>
#include <cstdint>

// Scratch: ping-through feature buffer and speed-estimate buffer.
// Sized for BF*N = 8*4096 = 32768 queries, C = 64.
#define MAX_Q (8 * 4096)
__device__ float g_cur[MAX_Q * 64];

// One warp per query. P = points this stage. FIRST: speed_est = 0, read external cur.
// LAST: write final output [q, 66] = (features 64, speed 2).
template <int P, bool FIRST, bool LAST>
__global__ __launch_bounds__(256) void speed_sampler_stage(
    const float* __restrict__ curIn,    // [BFN, 64] (only used when FIRST)
    const float* __restrict__ indices,  // [BFN, 2]
    const float* __restrict__ value,    // [BF*HW, 64]
    const float* __restrict__ we,       // [64, 2P]
    const float* __restrict__ be,       // [2P]
    const float* __restrict__ ww,       // [64, P]
    const float* __restrict__ bw,       // [P]
    const int* __restrict__ hsp_p, const int* __restrict__ wsp_p,
    float* __restrict__ g_sp,           // [BFN, 2] speed scratch (device scratch tail of g_cur? no: separate)
    float* __restrict__ out,            // [BFN, 66] (only when LAST)
    int BFN, int BFHW)
{
    constexpr int NCOL = 3 * P;  // cols 0..2P-1 = delta (x,y pairs), 2P..3P-1 = wt logits
    __shared__ float sW[64 * NCOL];
    __shared__ float sB[NCOL];
    __shared__ float sCur[8][64];
    __shared__ float sLogit[8][NCOL];

    const int tid = threadIdx.x;
    for (int i = tid; i < 64 * NCOL; i += blockDim.x) {
        int k = i / NCOL, c = i % NCOL;
        sW[i] = (c < 2 * P) ? we[k * (2 * P) + c] : ww[k * P + (c - 2 * P)];
    }
    if (tid < NCOL) sB[tid] = (tid < 2 * P) ? be[tid] : bw[tid - 2 * P];

    const int warp = tid >> 5, lane = tid & 31;
    const int q = blockIdx.x * 8 + warp;
    const int h = *hsp_p, w = *wsp_p;
    const int HW = h * w;
    const int BF = BFHW / HW;
    const int Nq = BFN / BF;
    __syncthreads();
    if (q >= BFN) return;

    // ---- load this query's 64-ch feature into shared ----
    const float* curSrc = FIRST ? curIn : g_cur;
    float2 c2 = *reinterpret_cast<const float2*>(curSrc + (size_t)q * 64 + 2 * lane);
    sCur[warp][2 * lane]     = c2.x;
    sCur[warp][2 * lane + 1] = c2.y;
    __syncwarp();

    // ---- tiny GEMM: 64 -> 3P (lanes 0..NCOL-1 each own a column) ----
    if (lane < NCOL) {
        float acc = sB[lane];
        #pragma unroll
        for (int k = 0; k < 64; k++) acc += sCur[warp][k] * sW[k * NCOL + lane];
        sLogit[warp][lane] = acc;
    }
    __syncwarp();

    // ---- softmax + argmax over P (all lanes redundantly, tiny) ----
    float wl[P];
    float m = -1e30f;
    int mid = 0;
    #pragma unroll
    for (int p = 0; p < P; p++) {
        wl[p] = sLogit[warp][2 * P + p];
        if (wl[p] > m) { m = wl[p]; mid = p; }  // strict > keeps first max (jnp.argmax)
    }
    float sum = 0.f;
    #pragma unroll
    for (int p = 0; p < P; p++) { wl[p] = expf(wl[p] - m); sum += wl[p]; }
    const float inv = 1.0f / sum;

    // ---- speed estimate: offset uses OLD speed; update with delta[argmax] ----
    float spx, spy;
    if (FIRST) { spx = 0.f; spy = 0.f; }
    else       { spx = g_sp[(size_t)q * 2]; spy = g_sp[(size_t)q * 2 + 1]; }
    const float nspx = spx + sLogit[warp][2 * mid];
    const float nspy = spy + sLogit[warp][2 * mid + 1];
    if (lane == 0) {
        if (LAST) {
            out[(size_t)q * 66 + 64] = nspx;
            out[(size_t)q * 66 + 65] = nspy;
        } else {
            g_sp[(size_t)q * 2]     = nspx;
            g_sp[(size_t)q * 2 + 1] = nspy;
        }
    }

    // ---- deformable sampling: P points x 4 bilinear corners, 2 ch per lane ----
    const int bf = q / Nq;
    const float* vbase = value + (size_t)bf * HW * 64 + 2 * lane;
    const float idx0 = indices[(size_t)q * 2];
    const float idx1 = indices[(size_t)q * 2 + 1];
    const float fh = (float)h, fw = (float)w;

    float2 acc = make_float2(0.f, 0.f);
    #pragma unroll
    for (int p = 0; p < P; p++) {
        const float dx = sLogit[warp][2 * p];
        const float dy = sLogit[warp][2 * p + 1];
        const float offx = spx + dx;
        const float offy = spy + dy;
        // loc = ref + offset*0.1/sp ; ref = idx/sp ; sp = [h, w]
        const float locx = idx0 / fh + (offx * 0.1f) / fh;
        const float locy = idx1 / fw + (offy * 0.1f) / fw;
        // grid_sample align_corners=False pixel coords
        const float x = locx * fw - 0.5f;
        const float y = locy * fh - 0.5f;
        const float x0f = floorf(x), y0f = floorf(y);
        const float fx = x - x0f, fy = y - y0f;
        const int x0 = (int)x0f, y0 = (int)y0f;

        float2 s = make_float2(0.f, 0.f);
        #pragma unroll
        for (int cy = 0; cy < 2; cy++) {
            #pragma unroll
            for (int cx = 0; cx < 2; cx++) {
                const int xi = x0 + cx, yi = y0 + cy;
                const bool valid = (xi >= 0) & (xi < w) & (yi >= 0) & (yi < h);
                const float cw = (cx ? fx : (1.f - fx)) * (cy ? fy : (1.f - fy));
                if (valid) {
                    const float2 v = *reinterpret_cast<const float2*>(
                        vbase + ((size_t)yi * w + xi) * 64);
                    s.x += v.x * cw;
                    s.y += v.y * cw;
                }
            }
        }
        const float wp = wl[p] * inv;
        acc.x += s.x * wp;
        acc.y += s.y * wp;
    }

    // ---- write new feature ----
    if (LAST) {
        *reinterpret_cast<float2*>(out + (size_t)q * 66 + 2 * lane) = acc;  // 66*q + 2*lane even -> 8B aligned
    } else {
        *reinterpret_cast<float2*>(g_cur + (size_t)q * 64 + 2 * lane) = acc;
    }
}

// Speed scratch lives as its own device array.
__device__ float g_speed[MAX_Q * 2];

template <bool FIRST, bool LAST>
static void launch_stage(int P, dim3 grid, dim3 block,
                         const float* curIn, const float* idxs, const float* val,
                         const float* we, const float* be,
                         const float* ww, const float* bw,
                         const int* hsp, const int* wsp,
                         float* sp_ptr, float* out, int BFN, int BFHW)
{
    switch (P) {
        case 1: speed_sampler_stage<1, FIRST, LAST><<<grid, block>>>(curIn, idxs, val, we, be, ww, bw, hsp, wsp, sp_ptr, out, BFN, BFHW); break;
        case 2: speed_sampler_stage<2, FIRST, LAST><<<grid, block>>>(curIn, idxs, val, we, be, ww, bw, hsp, wsp, sp_ptr, out, BFN, BFHW); break;
        case 3: speed_sampler_stage<3, FIRST, LAST><<<grid, block>>>(curIn, idxs, val, we, be, ww, bw, hsp, wsp, sp_ptr, out, BFN, BFHW); break;
        case 4: speed_sampler_stage<4, FIRST, LAST><<<grid, block>>>(curIn, idxs, val, we, be, ww, bw, hsp, wsp, sp_ptr, out, BFN, BFHW); break;
        case 6: speed_sampler_stage<6, FIRST, LAST><<<grid, block>>>(curIn, idxs, val, we, be, ww, bw, hsp, wsp, sp_ptr, out, BFN, BFHW); break;
        case 8: speed_sampler_stage<8, FIRST, LAST><<<grid, block>>>(curIn, idxs, val, we, be, ww, bw, hsp, wsp, sp_ptr, out, BFN, BFHW); break;
        default: break;
    }
}

extern "C" void kernel_launch(void* const* d_in, const int* in_sizes, int n_in,
                              void* d_out, int out_size)
{
    // Input order (setup_inputs dict insertion order):
    // 0: cur_features_dense [BF,N,C]   1: cur_indices_dense [BF,N,2]
    // 2: pre_value [BF,HW,1,C]         3: h_sp (int)   4: w_sp (int)
    // 5..8:  w_est1,b_est1,w_wt1,b_wt1
    // 9..12: w_est2,b_est2,w_wt2,b_wt2
    // 13..16:w_est3,b_est3,w_wt3,b_wt3
    const float* cur  = (const float*)d_in[0];
    const float* idxs = (const float*)d_in[1];
    const float* val  = (const float*)d_in[2];
    const int*   hsp  = (const int*)d_in[3];
    const int*   wsp  = (const int*)d_in[4];

    const int P1 = in_sizes[6] / 2;     // b_est1 = 2*P1
    const int P2 = in_sizes[10] / 2;
    const int P3 = in_sizes[14] / 2;
    const int C  = in_sizes[5] / in_sizes[6];   // (C*2P1)/(2P1)
    const int BFN  = in_sizes[0] / C;
    const int BFHW = in_sizes[2] / C;

    float* out = (float*)d_out;

    float* sp_ptr = nullptr;
    cudaGetSymbolAddress((void**)&sp_ptr, g_speed);

    dim3 block(256);
    dim3 grid((BFN + 7) / 8);

    // stage 1: reads external cur, speed_est starts at 0, writes g_cur/g_speed
    launch_stage<true, false>(P1, grid, block, cur, idxs, val,
                              (const float*)d_in[5], (const float*)d_in[6],
                              (const float*)d_in[7], (const float*)d_in[8],
                              hsp, wsp, sp_ptr, nullptr, BFN, BFHW);
    // stage 2: reads/writes g_cur, g_speed
    launch_stage<false, false>(P2, grid, block, nullptr, idxs, val,
                               (const float*)d_in[9], (const float*)d_in[10],
                               (const float*)d_in[11], (const float*)d_in[12],
                               hsp, wsp, sp_ptr, nullptr, BFN, BFHW);
    // stage 3: reads g_cur/g_speed, writes final out [BFN, C+2]
    launch_stage<false, true>(P3, grid, block, nullptr, idxs, val,
                              (const float*)d_in[13], (const float*)d_in[14],
                              (const float*)d_in[15], (const float*)d_in[16],
                              hsp, wsp, sp_ptr, out, BFN, BFHW);
}

// round 4
// speedup vs baseline: 1.9437x; 1.9437x over previous
#include <cuda_runtime.h>
#include <cstdint>

#define QPB 16   // queries per block: 8 warps x 2 half-warp queries

__device__ __forceinline__ void load_w(float* sW, float* sB,
    const float* __restrict__ we, const float* __restrict__ be,
    const float* __restrict__ ww, const float* __restrict__ bw,
    int P, int tid, int nthreads)
{
    const int NCOL = 3 * P;
    for (int i = tid; i < 64 * NCOL; i += nthreads) {
        int k = i / NCOL, c = i % NCOL;
        sW[i] = (c < 2 * P) ? we[k * (2 * P) + c] : ww[k * P + (c - 2 * P)];
    }
    if (tid < NCOL) sB[tid] = (tid < 2 * P) ? be[tid] : bw[tid - 2 * P];
}

// One stage for one query handled by a 16-lane half-warp; each lane owns 4 channels.
// Returns this lane's new float4 feature; updates spx/spy (same value in all lanes).
template <int P>
__device__ __forceinline__ float4 run_stage(
    int qw, int sl,
    const float* __restrict__ sW, const float* __restrict__ sB,
    float (*sCur)[64], float (*sLogit)[16],
    float& spx, float& spy,
    float idx0, float idx1, int h, int w,
    const float* __restrict__ vbase, bool active)
{
    constexpr int NCOL = 3 * P;

    // tiny GEMM 64 -> 3P: lanes 0..NCOL-1 of the half-warp each own a column
    if (sl < NCOL) {
        float a = sB[sl];
        #pragma unroll
        for (int k = 0; k < 64; k++) a += sCur[qw][k] * sW[k * NCOL + sl];
        sLogit[qw][sl] = a;
    }
    __syncwarp();

    // softmax + argmax over P (redundant per lane, tiny)
    float wl[P];
    float m = -1e30f; int mid = 0;
    #pragma unroll
    for (int p = 0; p < P; p++) {
        wl[p] = sLogit[qw][2 * P + p];
        if (wl[p] > m) { m = wl[p]; mid = p; }   // strict > => first max (jnp.argmax)
    }
    float sum = 0.f;
    #pragma unroll
    for (int p = 0; p < P; p++) { wl[p] = expf(wl[p] - m); sum += wl[p]; }
    const float inv = 1.0f / sum;

    // offsets use OLD speed; speed updated with delta[argmax]
    const float ospx = spx, ospy = spy;
    spx += sLogit[qw][2 * mid];
    spy += sLogit[qw][2 * mid + 1];

    const float fh = (float)h, fw = (float)w;
    float4 acc = make_float4(0.f, 0.f, 0.f, 0.f);

    #pragma unroll
    for (int p = 0; p < P; p++) {
        const float offx = ospx + sLogit[qw][2 * p];
        const float offy = ospy + sLogit[qw][2 * p + 1];
        const float locx = idx0 / fh + (offx * 0.1f) / fh;
        const float locy = idx1 / fw + (offy * 0.1f) / fw;
        const float x = locx * fw - 0.5f;
        const float y = locy * fh - 0.5f;
        const float x0f = floorf(x), y0f = floorf(y);
        const float fx = x - x0f, fy = y - y0f;
        const int x0 = (int)x0f, y0 = (int)y0f;

        float4 s = make_float4(0.f, 0.f, 0.f, 0.f);
        #pragma unroll
        for (int cy = 0; cy < 2; cy++) {
            #pragma unroll
            for (int cx = 0; cx < 2; cx++) {
                const int xi = x0 + cx, yi = y0 + cy;
                const bool valid = active & (xi >= 0) & (xi < w) & (yi >= 0) & (yi < h);
                const float cw = (cx ? fx : (1.f - fx)) * (cy ? fy : (1.f - fy));
                if (valid) {
                    const float4 v = *reinterpret_cast<const float4*>(
                        vbase + ((size_t)yi * w + xi) * 64);
                    s.x += v.x * cw; s.y += v.y * cw;
                    s.z += v.z * cw; s.w += v.w * cw;
                }
            }
        }
        const float wp = wl[p] * inv;
        acc.x += s.x * wp; acc.y += s.y * wp;
        acc.z += s.z * wp; acc.w += s.w * wp;
    }
    return acc;
}

template <int P1, int P2, int P3>
__global__ __launch_bounds__(256) void speed_sampler_fused(
    const float* __restrict__ curIn,    // [BFN, 64]
    const float* __restrict__ indices,  // [BFN, 2]
    const float* __restrict__ value,    // [BF*HW, 64]
    const float* __restrict__ we1, const float* __restrict__ be1,
    const float* __restrict__ ww1, const float* __restrict__ bw1,
    const float* __restrict__ we2, const float* __restrict__ be2,
    const float* __restrict__ ww2, const float* __restrict__ bw2,
    const float* __restrict__ we3, const float* __restrict__ be3,
    const float* __restrict__ ww3, const float* __restrict__ bw3,
    const int* __restrict__ hsp_p, const int* __restrict__ wsp_p,
    float* __restrict__ out,            // [BFN, 66]
    int BFN, int BFHW)
{
    constexpr int NC1 = 3 * P1, NC2 = 3 * P2, NC3 = 3 * P3;
    __shared__ float sW1[64 * NC1], sW2[64 * NC2], sW3[64 * NC3];
    __shared__ float sB1[NC1], sB2[NC2], sB3[NC3];
    __shared__ __align__(16) float sCur[QPB][64];
    __shared__ float sLogit[QPB][16];

    const int tid = threadIdx.x;
    load_w(sW1, sB1, we1, be1, ww1, bw1, P1, tid, blockDim.x);
    load_w(sW2, sB2, we2, be2, ww2, bw2, P2, tid, blockDim.x);
    load_w(sW3, sB3, we3, be3, ww3, bw3, P3, tid, blockDim.x);

    const int sl = tid & 15;            // sub-lane within half-warp
    const int qw = tid >> 4;            // query slot in block, 0..15
    const int q = blockIdx.x * QPB + qw;
    const int h = *hsp_p, w = *wsp_p;
    const int HW = h * w;
    const int BF = BFHW / HW;
    const int Nq = BFN / BF;
    const bool active = q < BFN;

    __syncthreads();

    float idx0 = 0.f, idx1 = 0.f;
    const float* vbase = value;
    if (active) {
        // load this query's feature: lane sl owns channels 4sl..4sl+3
        float4 c4 = *reinterpret_cast<const float4*>(curIn + (size_t)q * 64 + 4 * sl);
        *reinterpret_cast<float4*>(&sCur[qw][4 * sl]) = c4;
        idx0 = indices[(size_t)q * 2];
        idx1 = indices[(size_t)q * 2 + 1];
        const int bf = q / Nq;
        vbase = value + (size_t)bf * HW * 64 + 4 * sl;
    }
    float spx = 0.f, spy = 0.f;
    __syncwarp();

    float4 acc = run_stage<P1>(qw, sl, sW1, sB1, sCur, sLogit,
                               spx, spy, idx0, idx1, h, w, vbase, active);
    __syncwarp();
    if (active) *reinterpret_cast<float4*>(&sCur[qw][4 * sl]) = acc;
    __syncwarp();

    acc = run_stage<P2>(qw, sl, sW2, sB2, sCur, sLogit,
                        spx, spy, idx0, idx1, h, w, vbase, active);
    __syncwarp();
    if (active) *reinterpret_cast<float4*>(&sCur[qw][4 * sl]) = acc;
    __syncwarp();

    acc = run_stage<P3>(qw, sl, sW3, sB3, sCur, sLogit,
                        spx, spy, idx0, idx1, h, w, vbase, active);

    if (active) {
        // out row = 66 floats: 64 features + 2 speed. 4*sl within row; row base q*66
        // (q*66 + 4*sl) is always even -> 8B-aligned: use two float2 stores.
        float* o = out + (size_t)q * 66 + 4 * sl;
        *reinterpret_cast<float2*>(o)     = make_float2(acc.x, acc.y);
        *reinterpret_cast<float2*>(o + 2) = make_float2(acc.z, acc.w);
        if (sl == 0) {
            out[(size_t)q * 66 + 64] = spx;
            out[(size_t)q * 66 + 65] = spy;
        }
    }
}

extern "C" void kernel_launch(void* const* d_in, const int* in_sizes, int n_in,
                              void* d_out, int out_size)
{
    // 0: cur_features_dense [BF,N,C]   1: cur_indices_dense [BF,N,2]
    // 2: pre_value [BF,HW,1,C]         3: h_sp (int)   4: w_sp (int)
    // 5..8:  w_est1,b_est1,w_wt1,b_wt1
    // 9..12: w_est2,b_est2,w_wt2,b_wt2
    // 13..16:w_est3,b_est3,w_wt3,b_wt3
    const float* cur  = (const float*)d_in[0];
    const float* idxs = (const float*)d_in[1];
    const float* val  = (const float*)d_in[2];
    const int*   hsp  = (const int*)d_in[3];
    const int*   wsp  = (const int*)d_in[4];

    const int P1 = in_sizes[6] / 2;
    const int P2 = in_sizes[10] / 2;
    const int P3 = in_sizes[14] / 2;
    const int C  = in_sizes[5] / in_sizes[6];
    const int BFN  = in_sizes[0] / C;
    const int BFHW = in_sizes[2] / C;

    float* out = (float*)d_out;
    dim3 block(256);
    dim3 grid((BFN + QPB - 1) / QPB);

    if (P1 == 4 && P2 == 2 && P3 == 1) {
        speed_sampler_fused<4, 2, 1><<<grid, block>>>(
            cur, idxs, val,
            (const float*)d_in[5],  (const float*)d_in[6],
            (const float*)d_in[7],  (const float*)d_in[8],
            (const float*)d_in[9],  (const float*)d_in[10],
            (const float*)d_in[11], (const float*)d_in[12],
            (const float*)d_in[13], (const float*)d_in[14],
            (const float*)d_in[15], (const float*)d_in[16],
            hsp, wsp, out, BFN, BFHW);
    }
}

// round 6
// speedup vs baseline: 2.4198x; 1.2450x over previous
#include <cuda_runtime.h>
#include <cstdint>

#define QPB 16   // queries per block: 8 warps x 2 half-warp queries

// Padded per-lane weight-block strides (words). Requirement: 16B aligned
// (stride % 4 == 0) and stride % 8 == 4 so the 8-lane LDS.128 phases tile
// all 32 banks conflict-free.
template <int P> struct WStride { static constexpr int v = ((4 * 3 * P) % 8 == 4) ? (4 * 3 * P) : (4 * 3 * P + 4); };
// P=4: 48 -> 52 ; P=2: 24 -> 28 ; P=1: 12 -> 16 (16%8=0!) -> need 20
template <> struct WStride<1> { static constexpr int v = 20; };

// Fill per-lane weight blocks: sWb[(k>>2)*STRIDE + c*4 + (k&3)] = W[k][c]
// where W cols 0..2P-1 = w_est, 2P..3P-1 = w_wt. sB[c] = bias.
__device__ __forceinline__ void load_wb(float* sWb, float* sB, int STRIDE,
    const float* __restrict__ we, const float* __restrict__ be,
    const float* __restrict__ ww, const float* __restrict__ bw,
    int P, int tid, int nthreads)
{
    const int NCOL = 3 * P;
    for (int i = tid; i < 64 * NCOL; i += nthreads) {
        int k = i / NCOL, c = i % NCOL;
        float v = (c < 2 * P) ? we[k * (2 * P) + c] : ww[k * P + (c - 2 * P)];
        sWb[(k >> 2) * STRIDE + c * 4 + (k & 3)] = v;
    }
    if (tid < NCOL) sB[tid] = (tid < 2 * P) ? be[tid] : bw[tid - 2 * P];
}

// One stage for one query on a 16-lane half-warp; lane owns 4 channels (c4).
// Returns new feature c4; updates spx/spy (identical in all lanes).
template <int P>
__device__ __forceinline__ float4 run_stage(
    float4 c4, int sl,
    const float* __restrict__ sWb,   // lane blocks, stride WStride<P>::v
    const float* __restrict__ sB,
    float& spx, float& spy,
    float base_x, float base_y, float sc_x, float sc_y,
    int h, int w,
    const float* __restrict__ vbase, bool active)
{
    constexpr int NCOL = 3 * P;
    constexpr int STRIDE = WStride<P>::v;

    // ---- register GEMM: partial[j] = c4 . W[4sl..4sl+3][j] ----
    const float4* blk = reinterpret_cast<const float4*>(sWb + sl * STRIDE);
    float lg[NCOL];
    #pragma unroll
    for (int j = 0; j < NCOL; j++) {
        const float4 wv = blk[j];
        lg[j] = fmaf(c4.x, wv.x, fmaf(c4.y, wv.y, fmaf(c4.z, wv.z, c4.w * wv.w)));
    }
    // butterfly reduce across the 16-lane half-warp (xor < 16 stays in half)
    #pragma unroll
    for (int step = 1; step < 16; step <<= 1) {
        #pragma unroll
        for (int j = 0; j < NCOL; j++)
            lg[j] += __shfl_xor_sync(0xffffffffu, lg[j], step);
    }
    #pragma unroll
    for (int j = 0; j < NCOL; j++) lg[j] += sB[j];

    // ---- softmax + argmax over P ----
    float wl[P];
    float m = -1e30f; int mid = 0;
    #pragma unroll
    for (int p = 0; p < P; p++) {
        wl[p] = lg[2 * P + p];
        if (wl[p] > m) { m = wl[p]; mid = p; }   // strict > => first max (jnp.argmax)
    }
    float sum = 0.f;
    #pragma unroll
    for (int p = 0; p < P; p++) { wl[p] = expf(wl[p] - m); sum += wl[p]; }
    const float inv = 1.0f / sum;

    // offsets use OLD speed; speed updated with delta[argmax]
    const float bx = fmaf(spx, sc_x, base_x);   // fold old speed into point base
    const float by = fmaf(spy, sc_y, base_y);
    spx += lg[2 * mid];
    spy += lg[2 * mid + 1];

    float4 acc = make_float4(0.f, 0.f, 0.f, 0.f);
    #pragma unroll
    for (int p = 0; p < P; p++) {
        const float x = fmaf(lg[2 * p],     sc_x, bx);
        const float y = fmaf(lg[2 * p + 1], sc_y, by);
        const float x0f = floorf(x), y0f = floorf(y);
        const float fx = x - x0f, fy = y - y0f;
        const int x0 = (int)x0f, y0 = (int)y0f;

        float4 s = make_float4(0.f, 0.f, 0.f, 0.f);
        #pragma unroll
        for (int cy = 0; cy < 2; cy++) {
            #pragma unroll
            for (int cx = 0; cx < 2; cx++) {
                const int xi = x0 + cx, yi = y0 + cy;
                const bool valid = active & (xi >= 0) & (xi < w) & (yi >= 0) & (yi < h);
                const float cw = (cx ? fx : (1.f - fx)) * (cy ? fy : (1.f - fy));
                if (valid) {
                    const float4 v = *reinterpret_cast<const float4*>(
                        vbase + ((size_t)yi * w + xi) * 64);
                    s.x += v.x * cw; s.y += v.y * cw;
                    s.z += v.z * cw; s.w += v.w * cw;
                }
            }
        }
        const float wp = wl[p] * inv;
        acc.x += s.x * wp; acc.y += s.y * wp;
        acc.z += s.z * wp; acc.w += s.w * wp;
    }
    return acc;
}

template <int P1, int P2, int P3>
__global__ __launch_bounds__(256) void speed_sampler_fused(
    const float* __restrict__ curIn,    // [BFN, 64]
    const float* __restrict__ indices,  // [BFN, 2]
    const float* __restrict__ value,    // [BF*HW, 64]
    const float* __restrict__ we1, const float* __restrict__ be1,
    const float* __restrict__ ww1, const float* __restrict__ bw1,
    const float* __restrict__ we2, const float* __restrict__ be2,
    const float* __restrict__ ww2, const float* __restrict__ bw2,
    const float* __restrict__ we3, const float* __restrict__ be3,
    const float* __restrict__ ww3, const float* __restrict__ bw3,
    const int* __restrict__ hsp_p, const int* __restrict__ wsp_p,
    float* __restrict__ out,            // [BFN, 66]
    int BFN, int BFHW)
{
    constexpr int S1 = WStride<P1>::v, S2 = WStride<P2>::v, S3 = WStride<P3>::v;
    __shared__ __align__(16) float sWb1[16 * S1];
    __shared__ __align__(16) float sWb2[16 * S2];
    __shared__ __align__(16) float sWb3[16 * S3];
    __shared__ float sB1[3 * P1], sB2[3 * P2], sB3[3 * P3];

    const int tid = threadIdx.x;
    load_wb(sWb1, sB1, S1, we1, be1, ww1, bw1, P1, tid, blockDim.x);
    load_wb(sWb2, sB2, S2, we2, be2, ww2, bw2, P2, tid, blockDim.x);
    load_wb(sWb3, sB3, S3, we3, be3, ww3, bw3, P3, tid, blockDim.x);

    const int sl = tid & 15;            // sub-lane within half-warp
    const int qw = tid >> 4;            // query slot in block, 0..15
    const int q = blockIdx.x * QPB + qw;
    const int h = *hsp_p, w = *wsp_p;
    const int HW = h * w;
    const int BF = BFHW / HW;
    const int Nq = BFN / BF;
    const bool active = q < BFN;

    __syncthreads();

    // x = (idx0 + 0.1*off_x) * (w/h) - 0.5 ; y = (idx1 + 0.1*off_y) * (h/w) - 0.5
    const float fh = (float)h, fw = (float)w;
    const float rwh = fw / fh, rhw = fh / fw;
    const float sc_x = 0.1f * rwh, sc_y = 0.1f * rhw;

    float4 c4 = make_float4(0.f, 0.f, 0.f, 0.f);
    float base_x = 0.f, base_y = 0.f;
    const float* vbase = value;
    if (active) {
        c4 = *reinterpret_cast<const float4*>(curIn + (size_t)q * 64 + 4 * sl);
        const float idx0 = indices[(size_t)q * 2];
        const float idx1 = indices[(size_t)q * 2 + 1];
        base_x = fmaf(idx0, rwh, -0.5f);
        base_y = fmaf(idx1, rhw, -0.5f);
        const int bf = q / Nq;
        vbase = value + (size_t)bf * HW * 64 + 4 * sl;
    }
    float spx = 0.f, spy = 0.f;

    c4 = run_stage<P1>(c4, sl, sWb1, sB1, spx, spy, base_x, base_y, sc_x, sc_y, h, w, vbase, active);
    c4 = run_stage<P2>(c4, sl, sWb2, sB2, spx, spy, base_x, base_y, sc_x, sc_y, h, w, vbase, active);
    c4 = run_stage<P3>(c4, sl, sWb3, sB3, spx, spy, base_x, base_y, sc_x, sc_y, h, w, vbase, active);

    if (active) {
        // out row = 66 floats: 64 features + 2 speed. (q*66 + 4*sl) is even -> 8B aligned.
        float* o = out + (size_t)q * 66 + 4 * sl;
        *reinterpret_cast<float2*>(o)     = make_float2(c4.x, c4.y);
        *reinterpret_cast<float2*>(o + 2) = make_float2(c4.z, c4.w);
        if (sl == 0) {
            out[(size_t)q * 66 + 64] = spx;
            out[(size_t)q * 66 + 65] = spy;
        }
    }
}

extern "C" void kernel_launch(void* const* d_in, const int* in_sizes, int n_in,
                              void* d_out, int out_size)
{
    // 0: cur_features_dense [BF,N,C]   1: cur_indices_dense [BF,N,2]
    // 2: pre_value [BF,HW,1,C]         3: h_sp (int)   4: w_sp (int)
    // 5..8:  w_est1,b_est1,w_wt1,b_wt1
    // 9..12: w_est2,b_est2,w_wt2,b_wt2
    // 13..16:w_est3,b_est3,w_wt3,b_wt3
    const float* cur  = (const float*)d_in[0];
    const float* idxs = (const float*)d_in[1];
    const float* val  = (const float*)d_in[2];
    const int*   hsp  = (const int*)d_in[3];
    const int*   wsp  = (const int*)d_in[4];

    const int P1 = in_sizes[6] / 2;
    const int P2 = in_sizes[10] / 2;
    const int P3 = in_sizes[14] / 2;
    const int C  = in_sizes[5] / in_sizes[6];
    const int BFN  = in_sizes[0] / C;
    const int BFHW = in_sizes[2] / C;

    float* out = (float*)d_out;
    dim3 block(256);
    dim3 grid((BFN + QPB - 1) / QPB);

    if (P1 == 4 && P2 == 2 && P3 == 1) {
        speed_sampler_fused<4, 2, 1><<<grid, block>>>(
            cur, idxs, val,
            (const float*)d_in[5],  (const float*)d_in[6],
            (const float*)d_in[7],  (const float*)d_in[8],
            (const float*)d_in[9],  (const float*)d_in[10],
            (const float*)d_in[11], (const float*)d_in[12],
            (const float*)d_in[13], (const float*)d_in[14],
            (const float*)d_in[15], (const float*)d_in[16],
            hsp, wsp, out, BFN, BFHW);
    }
}